// round 14
// baseline (speedup 1.0000x reference)
#include <cuda_runtime.h>
#include <math.h>

#define N_NODES 30000
#define MM      16
#define NODEF   128
#define NM      (N_NODES*MM)   // 480000

typedef unsigned long long ull;

// ---------------- f32x2 packed helpers (sm_103a) ---------------------------
__device__ __forceinline__ ull pack2(float x, float y) {
    ull r; asm("mov.b64 %0, {%1, %2};" : "=l"(r) : "f"(x), "f"(y)); return r;
}
__device__ __forceinline__ void fma2(ull& d, ull a, ull b) {
    asm("fma.rn.f32x2 %0, %1, %2, %0;" : "+l"(d) : "l"(a), "l"(b));
}
__device__ __forceinline__ float2 unpack2(ull v) {
    float2 r; asm("mov.b64 {%0, %1}, %2;" : "=f"(r.x), "=f"(r.y) : "l"(v)); return r;
}
__device__ __forceinline__ float softplusf(float x) {
    float ax = fabsf(x);
    return fmaxf(x, 0.f) + __logf(1.f + __expf(-ax));
}

// ---------------- scratch (device globals; no allocations) ----------------
__device__ float  g_node[N_NODES*NODEF];
__device__ float  g_S[N_NODES*NODEF];
__device__ float  g_P[N_NODES*NODEF];
__device__ float  g_summed[N_NODES*NODEF];
__device__ float  g_Q[N_NODES*NODEF];
__device__ double g_sum1[3][NODEF], g_sq1[3][NODEF];
__device__ double g_sum2[3][NODEF], g_sq2[3][NODEF];
__device__ float  g_We[5*NODEF], g_wd[NODEF], g_cvec[NODEF];
__device__ float  g_logits[NM];
__device__ float  g_bmax[2048], g_bsum[2048];
__device__ float  g_gmax, g_ginv;
__device__ float  g_tp;

// ---------------- embedding: node = node_fea @ emb_W + emb_b --------------
__global__ void k_embed(const float* __restrict__ nf,
                        const float* __restrict__ W,
                        const float* __restrict__ b) {
    __shared__ float s[19];
    int n = blockIdx.x;
    if (threadIdx.x < 19) s[threadIdx.x] = nf[n*19 + threadIdx.x];
    __syncthreads();
    int c = threadIdx.x;
    float acc = b[c];
    #pragma unroll
    for (int k = 0; k < 19; k++) acc += s[k] * W[k*128 + c];
    g_node[n*128 + c] = acc;
}

__global__ void k_zero() {
    int i = threadIdx.x;                 // 384 threads cover 3*128
    int l = i >> 7, c = i & 127;
    g_sum1[l][c] = 0.0; g_sq1[l][c] = 0.0;
    g_sum2[l][c] = 0.0; g_sq2[l][c] = 0.0;
}

// ------- conv GEMM: S = node@Wself + bias, P = node@Wnbr (cols 0..127) ----
__global__ __launch_bounds__(256) void k_convmm(const float* __restrict__ Wl,
                                                const float* __restrict__ bl,
                                                int upd,
                                                const float* __restrict__ g2,
                                                const float* __restrict__ b2v,
                                                const double* __restrict__ sum2,
                                                const double* __restrict__ sq2) {
    __shared__ float sn[16*128];
    __shared__ float ssc[128], ssh[128];
    int tid = threadIdx.x;
    int r0  = blockIdx.x * 16;
    if (upd) {
        if (tid < 128) {
            double mean = sum2[tid] * (1.0/(double)N_NODES);
            double var  = sq2[tid]  * (1.0/(double)N_NODES) - mean*mean;
            float  sc   = g2[tid] * (float)(1.0 / sqrt(var + 1e-5));
            ssc[tid] = sc;
            ssh[tid] = b2v[tid] - (float)mean * sc;
        }
        __syncthreads();
        for (int i = tid; i < 2048; i += 256) {
            int c = i & 127;
            float x = g_node[r0*128 + i]
                    + g_summed[r0*128 + i]*ssc[c] + ssh[c];
            float v = softplusf(x);
            g_node[r0*128 + i] = v;
            sn[i] = v;
        }
    } else {
        for (int i = tid; i < 2048; i += 256) sn[i] = g_node[r0*128 + i];
    }
    __syncthreads();
    int half = tid >> 7, c = tid & 127;
    const float* W = Wl + (half*128)*256 + c;   // row stride 256, col c
    float acc[16];
    float bi = half ? 0.f : bl[c];
    #pragma unroll
    for (int r = 0; r < 16; r++) acc[r] = bi;
    #pragma unroll 2
    for (int k = 0; k < 128; k += 2) {
        float w0 = W[k*256], w1 = W[(k+1)*256];
        #pragma unroll
        for (int r = 0; r < 16; r++) {
            float2 h = *(const float2*)&sn[r*128 + k];
            acc[r] += h.x*w0 + h.y*w1;
        }
    }
    float* out = half ? g_P : g_S;
    #pragma unroll
    for (int r = 0; r < 16; r++) out[(r0+r)*128 + c] = acc[r];
}

// -------- BN1 statistics; 256 threads = 2 half-blocks of 128 rows each ----
__global__ __launch_bounds__(256) void k_stats(const float* __restrict__ Wl,
                                               const int*   __restrict__ idx,
                                               const float* __restrict__ ef,
                                               double* __restrict__ sum1,
                                               double* __restrict__ sq1) {
    int tid = threadIdx.x;
    int c   = tid & 127;
    int hh  = tid >> 7;                 // half: rows hh*128 .. hh*128+127
    int r0  = blockIdx.x * 256;
    __shared__ int   sidx[256];
    __shared__ float sef[256][5];
    if (tid < 256) {
        int id = idx[r0 + tid];
        sidx[tid] = (id < 0) ? id + N_NODES : id;
    }
    for (int i = tid; i < 1280; i += 256) sef[i/5][i%5] = ef[r0*5 + i];
    __syncthreads();
    float we[5];
    #pragma unroll
    for (int e = 0; e < 5; e++) we[e] = Wl[(256+e)*256 + c];
    float fs = 0.f, fq = 0.f;
    int n0 = (r0 >> 4) + hh*8;
    int m0 = hh*128;
    for (int g = 0; g < 8; g++) {
        float sv = g_S[(n0+g)*128 + c];
        #pragma unroll 4
        for (int m = 0; m < 16; m++) {
            int row = m0 + g*16 + m;
            float v = sv + g_P[sidx[row]*128 + c];
            #pragma unroll
            for (int e = 0; e < 5; e++) v += sef[row][e] * we[e];
            fs += v; fq += v*v;
        }
    }
    // combine the two halves per channel in shared, single atomic per channel
    __shared__ float rs[256], rq[256];
    rs[tid] = fs; rq[tid] = fq;
    __syncthreads();
    if (tid < 128) {
        double S = (double)rs[tid] + (double)rs[tid + 128];
        double Q = (double)rq[tid] + (double)rq[tid + 128];
        atomicAdd(&sum1[tid], S);
        atomicAdd(&sq1[tid],  Q);
    }
}

// ---- 8 nodes/block: summed + BN2 stats (fused colreduce), BN1 inline -----
__global__ __launch_bounds__(128) void k_aggregate(const float* __restrict__ Wl,
                                                   const int*   __restrict__ idx,
                                                   const float* __restrict__ ef,
                                                   const float* __restrict__ g1,
                                                   const float* __restrict__ b1v,
                                                   const double* __restrict__ sum1,
                                                   const double* __restrict__ sq1,
                                                   double* __restrict__ sum2,
                                                   double* __restrict__ sq2) {
    int c  = threadIdx.x;
    int n0 = blockIdx.x * 8;
    __shared__ int   sidx[128];
    __shared__ float smask[128];
    __shared__ float sef[128][5];
    {
        int id = idx[n0*16 + c];
        sidx[c]  = (id < 0) ? id + N_NODES : id;
        smask[c] = (id < 0) ? 0.f : 1.f;
    }
    for (int i = c; i < 640; i += 128) sef[i/5][i%5] = ef[n0*80 + i];
    __syncthreads();
    float we[5];
    #pragma unroll
    for (int e = 0; e < 5; e++) we[e] = Wl[(256+e)*256 + c];
    double mean = sum1[c] * (1.0/(double)NM);
    double var  = sq1[c]  * (1.0/(double)NM) - mean*mean;
    float  sc   = g1[c] * (float)(1.0 / sqrt(var + 1e-5));
    float  sh   = b1v[c] - (float)mean * sc;

    float s = 0.f, q = 0.f;
    for (int g = 0; g < 8; g++) {
        float sv = g_S[(n0+g)*128 + c];
        float acc = 0.f;
        #pragma unroll 4
        for (int m = 0; m < 16; m++) {
            int row = g*16 + m;
            float v = sv + g_P[sidx[row]*128 + c];
            #pragma unroll
            for (int e = 0; e < 5; e++) v += sef[row][e] * we[e];
            float a = v*sc + sh;
            float f = __fdividef(smask[row], 1.f + __expf(-a));
            acc += f*f;
        }
        g_summed[(n0+g)*128 + c] = acc;
        s += acc; q += acc*acc;
    }
    atomicAdd(&sum2[c], (double)s);
    atomicAdd(&sq2[c],  (double)q);
}

// ---------------- pi prep: fold tiled/repeated columns of W1 --------------
__global__ void k_piprep(const float* __restrict__ W1,
                         const float* __restrict__ b1,
                         const unsigned* __restrict__ tpp) {
    int c = threadIdx.x;
    unsigned u = *tpp;
    int iv = (int)u;
    float tp = (iv > -1000000 && iv < 1000000) ? (float)iv : __int_as_float(iv);
    if (c == 0) g_tp = tp;
    #pragma unroll
    for (int e = 0; e < 5; e++)
        g_We[e*128 + c] = W1[(128+e)*128 + c] + W1[(133+e)*128 + c];
    float wd = 0.f, ct = 0.f;
    for (int r = 138; r < 143; r++) wd += W1[r*128 + c];
    for (int r = 143; r < 148; r++) ct += W1[r*128 + c];
    g_wd[c]   = wd;
    g_cvec[c] = b1[c] + tp*ct;
}

// Q = update(node) @ W1[0:128] + cvec
__global__ __launch_bounds__(128) void k_qgemm(const float* __restrict__ W1,
                                               const float* __restrict__ g2,
                                               const float* __restrict__ b2v,
                                               const double* __restrict__ sum2,
                                               const double* __restrict__ sq2) {
    __shared__ float sn[2048];
    __shared__ float ssc[128], ssh[128];
    int tid = threadIdx.x;
    int r0  = blockIdx.x * 16;
    {
        double mean = sum2[tid] * (1.0/(double)N_NODES);
        double var  = sq2[tid]  * (1.0/(double)N_NODES) - mean*mean;
        float  scv  = g2[tid] * (float)(1.0 / sqrt(var + 1e-5));
        ssc[tid] = scv;
        ssh[tid] = b2v[tid] - (float)mean * scv;
    }
    __syncthreads();
    for (int i = tid; i < 2048; i += 128) {
        int c = i & 127;
        float x = g_node[r0*128 + i]
                + g_summed[r0*128 + i]*ssc[c] + ssh[c];
        sn[i] = softplusf(x);
    }
    __syncthreads();
    int c = tid;
    float cv = g_cvec[c];
    float acc[16];
    #pragma unroll
    for (int r = 0; r < 16; r++) acc[r] = cv;
    #pragma unroll 2
    for (int k = 0; k < 128; k += 2) {
        float w0 = W1[k*128 + c], w1 = W1[(k+1)*128 + c];
        #pragma unroll
        for (int r = 0; r < 16; r++) {
            float2 h = *(const float2*)&sn[r*128 + k];
            acc[r] += h.x*w0 + h.y*w1;
        }
    }
    #pragma unroll
    for (int r = 0; r < 16; r++) g_Q[(r0+r)*128 + c] = acc[r];
}

// ----------- fused pi MLP: 32 rows/block, 256 threads, 32KB smem ----------
__global__ __launch_bounds__(256) void k_pimlp(const int*   __restrict__ idx,
                                               const float* __restrict__ ef,
                                               const float* __restrict__ dist,
                                               const float* __restrict__ W2,
                                               const float* __restrict__ b2,
                                               const float* __restrict__ W3,
                                               const float* __restrict__ b3,
                                               const float* __restrict__ w4,
                                               const float* __restrict__ b4) {
    extern __shared__ float sm[];
    float* hA = sm;             // 32*128: h1, then h2 half1
    float* hB = sm + 32*128;    // 32*128: h2 half0, then h3
    __shared__ int   sidx[32];
    __shared__ float sdist[32];
    __shared__ float sef[32][5];
    int tid = threadIdx.x;
    int r0  = blockIdx.x * 32;
    if (tid < 32) { sidx[tid] = idx[r0 + tid]; sdist[tid] = dist[r0 + tid]; }
    if (tid < 160) sef[tid/5][tid%5] = ef[r0*5 + tid];
    __syncthreads();

    // stage 1
    {
        int j = tid & 127, rh = tid >> 7;
        float we0 = g_We[j], we1 = g_We[128+j], we2 = g_We[256+j],
              we3 = g_We[384+j], we4 = g_We[512+j];
        float wd = g_wd[j];
        for (int r = rh*16; r < rh*16 + 16; r++) {
            int id = sidx[r];
            int p  = (id < 0) ? id + N_NODES : id;
            float v = g_Q[p*128 + j];
            v += sef[r][0]*we0 + sef[r][1]*we1 + sef[r][2]*we2
               + sef[r][3]*we3 + sef[r][4]*we4;
            v += sdist[r]*wd;
            hA[r*128 + j] = fmaxf(v, 0.f);
        }
    }
    __syncthreads();

    int cb = (tid & 31) * 4;
    int rb = (tid >> 5) * 4;

    // ---- stage 2: both halves in one pass over k -------------------------
    {
        ull acc2[4][4];
        #pragma unroll
        for (int r = 0; r < 4; r++)
            #pragma unroll
            for (int q = 0; q < 4; q++) acc2[r][q] = 0ull;
        const float* W2a = W2 + cb;
        const float* W2b = W2 + 128 + cb;
        #pragma unroll 2
        for (int k = 0; k < 128; k += 2) {
            ulonglong2 wa0 = *(const ulonglong2*)(W2a + k*256);
            ulonglong2 wa1 = *(const ulonglong2*)(W2a + (k+1)*256);
            ulonglong2 wb0 = *(const ulonglong2*)(W2b + k*256);
            ulonglong2 wb1 = *(const ulonglong2*)(W2b + (k+1)*256);
            #pragma unroll
            for (int r = 0; r < 4; r++) {
                float2 h = *(const float2*)&hA[(rb+r)*128 + k];
                ull ha = pack2(h.x, h.x);
                ull hb = pack2(h.y, h.y);
                fma2(acc2[r][0], ha, wa0.x); fma2(acc2[r][1], ha, wa0.y);
                fma2(acc2[r][2], ha, wb0.x); fma2(acc2[r][3], ha, wb0.y);
                fma2(acc2[r][0], hb, wa1.x); fma2(acc2[r][1], hb, wa1.y);
                fma2(acc2[r][2], hb, wb1.x); fma2(acc2[r][3], hb, wb1.y);
            }
        }
        __syncthreads();
        const float2 ba0 = *(const float2*)&b2[cb];
        const float2 ba1 = *(const float2*)&b2[cb + 2];
        const float2 bb0 = *(const float2*)&b2[128 + cb];
        const float2 bb1 = *(const float2*)&b2[128 + cb + 2];
        #pragma unroll
        for (int r = 0; r < 4; r++) {
            float2 a0 = unpack2(acc2[r][0]);
            float2 a1 = unpack2(acc2[r][1]);
            float2 a2 = unpack2(acc2[r][2]);
            float2 a3 = unpack2(acc2[r][3]);
            float4 o0, o1;
            o0.x = fmaxf(a0.x + ba0.x, 0.f);
            o0.y = fmaxf(a0.y + ba0.y, 0.f);
            o0.z = fmaxf(a1.x + ba1.x, 0.f);
            o0.w = fmaxf(a1.y + ba1.y, 0.f);
            o1.x = fmaxf(a2.x + bb0.x, 0.f);
            o1.y = fmaxf(a2.y + bb0.y, 0.f);
            o1.z = fmaxf(a3.x + bb1.x, 0.f);
            o1.w = fmaxf(a3.y + bb1.y, 0.f);
            *(float4*)&hB[(rb+r)*128 + cb] = o0;
            *(float4*)&hA[(rb+r)*128 + cb] = o1;
        }
    }
    __syncthreads();

    // ---- stage 3: one pass over 256 k (hB then hA) -----------------------
    ull acc3[4][2];
    #pragma unroll
    for (int r = 0; r < 4; r++) { acc3[r][0] = 0ull; acc3[r][1] = 0ull; }
    {
        const float* W3c = W3 + cb;
        #pragma unroll 2
        for (int k = 0; k < 128; k += 2) {
            ulonglong2 w0 = *(const ulonglong2*)(W3c + k*128);
            ulonglong2 w1 = *(const ulonglong2*)(W3c + (k+1)*128);
            #pragma unroll
            for (int r = 0; r < 4; r++) {
                float2 h = *(const float2*)&hB[(rb+r)*128 + k];
                ull ha = pack2(h.x, h.x);
                ull hb = pack2(h.y, h.y);
                fma2(acc3[r][0], ha, w0.x); fma2(acc3[r][1], ha, w0.y);
                fma2(acc3[r][0], hb, w1.x); fma2(acc3[r][1], hb, w1.y);
            }
        }
        const float* W3d = W3 + 128*128 + cb;
        #pragma unroll 2
        for (int k = 0; k < 128; k += 2) {
            ulonglong2 w0 = *(const ulonglong2*)(W3d + k*128);
            ulonglong2 w1 = *(const ulonglong2*)(W3d + (k+1)*128);
            #pragma unroll
            for (int r = 0; r < 4; r++) {
                float2 h = *(const float2*)&hA[(rb+r)*128 + k];
                ull ha = pack2(h.x, h.x);
                ull hb = pack2(h.y, h.y);
                fma2(acc3[r][0], ha, w0.x); fma2(acc3[r][1], ha, w0.y);
                fma2(acc3[r][0], hb, w1.x); fma2(acc3[r][1], hb, w1.y);
            }
        }
    }
    __syncthreads();

    {
        const float2 bb0 = *(const float2*)&b3[cb];
        const float2 bb1 = *(const float2*)&b3[cb + 2];
        #pragma unroll
        for (int r = 0; r < 4; r++) {
            float2 a0 = unpack2(acc3[r][0]);
            float2 a1 = unpack2(acc3[r][1]);
            float4 o;
            o.x = fmaxf(a0.x + bb0.x, 0.f);
            o.y = fmaxf(a0.y + bb0.y, 0.f);
            o.z = fmaxf(a1.x + bb1.x, 0.f);
            o.w = fmaxf(a1.y + bb1.y, 0.f);
            *(float4*)&hB[(rb+r)*128 + cb] = o;
        }
    }
    __syncthreads();

    // stage 4: logits + validity mask
    {
        int warp = tid >> 5, lane = tid & 31;
        float w4a = w4[lane], w4b = w4[lane+32], w4c = w4[lane+64], w4d = w4[lane+96];
        float tp = g_tp;
        for (int r = warp*4; r < warp*4 + 4; r++) {
            const float* h = &hB[r*128];
            float v = h[lane]*w4a + h[lane+32]*w4b + h[lane+64]*w4c + h[lane+96]*w4d;
            #pragma unroll
            for (int o = 16; o > 0; o >>= 1) v += __shfl_down_sync(0xffffffffu, v, o);
            if (lane == 0) {
                float lg = v + b4[0];
                int id = sidx[r];
                if (!(id >= 0 && sef[r][4] <= tp)) lg -= 1e8f;
                g_logits[r0 + r] = lg;
            }
        }
    }
}

// ---------------- global masked softmax over 480000 logits ----------------
__global__ void k_smax1() {
    __shared__ float red[256];
    int tid = threadIdx.x;
    int i = blockIdx.x*256 + tid;
    float v = g_logits[i];
    red[tid] = v; __syncthreads();
    for (int s = 128; s > 0; s >>= 1) {
        if (tid < s) red[tid] = fmaxf(red[tid], red[tid+s]);
        __syncthreads();
    }
    float bm = red[0];
    __syncthreads();
    float e = __expf(v - bm);
    red[tid] = e; __syncthreads();
    for (int s = 128; s > 0; s >>= 1) {
        if (tid < s) red[tid] += red[tid+s];
        __syncthreads();
    }
    if (tid == 0) { g_bmax[blockIdx.x] = bm; g_bsum[blockIdx.x] = red[0]; }
}

__global__ void k_smax2(int nb) {
    __shared__ float red[256];
    int tid = threadIdx.x;
    float m = -3.4e38f;
    for (int i = tid; i < nb; i += 256) m = fmaxf(m, g_bmax[i]);
    red[tid] = m; __syncthreads();
    for (int s = 128; s > 0; s >>= 1) {
        if (tid < s) red[tid] = fmaxf(red[tid], red[tid+s]);
        __syncthreads();
    }
    float gm = red[0];
    __syncthreads();
    float su = 0.f;
    for (int i = tid; i < nb; i += 256) su += g_bsum[i]*__expf(g_bmax[i] - gm);
    red[tid] = su; __syncthreads();
    for (int s = 128; s > 0; s >>= 1) {
        if (tid < s) red[tid] += red[tid+s];
        __syncthreads();
    }
    if (tid == 0) { g_gmax = gm; g_ginv = 1.0f / red[0]; }
}

__global__ void k_smax3(float* __restrict__ out) {
    int i = blockIdx.x*256 + threadIdx.x;
    out[i] = __expf(g_logits[i] - g_gmax) * g_ginv;
}

// --------------------------------- launch ---------------------------------
extern "C" void kernel_launch(void* const* d_in, const int* in_sizes, int n_in,
                              void* d_out, int out_size) {
    const float* node_fea = (const float*)d_in[0];
    const float* edge_fea = (const float*)d_in[1];
    const int*   idx      = (const int*)  d_in[2];
    const float* distance = (const float*)d_in[3];
    const unsigned* tp_ptr = (const unsigned*)d_in[4];
    const float* emb_W = (const float*)d_in[5];
    const float* emb_b = (const float*)d_in[6];
    const float* convW = (const float*)d_in[7];
    const float* convB = (const float*)d_in[8];
    const float* bn1g  = (const float*)d_in[9];
    const float* bn1b  = (const float*)d_in[10];
    const float* bn2g  = (const float*)d_in[11];
    const float* bn2b  = (const float*)d_in[12];
    const float* W1 = (const float*)d_in[13];
    const float* b1 = (const float*)d_in[14];
    const float* W2 = (const float*)d_in[15];
    const float* b2 = (const float*)d_in[16];
    const float* W3 = (const float*)d_in[17];
    const float* b3 = (const float*)d_in[18];
    const float* w4 = (const float*)d_in[19];
    const float* b4 = (const float*)d_in[20];
    float* out = (float*)d_out;

    double *sum1p, *sq1p, *sum2p, *sq2p;
    cudaGetSymbolAddress((void**)&sum1p, g_sum1);
    cudaGetSymbolAddress((void**)&sq1p,  g_sq1);
    cudaGetSymbolAddress((void**)&sum2p, g_sum2);
    cudaGetSymbolAddress((void**)&sq2p,  g_sq2);

    k_embed<<<N_NODES, 128>>>(node_fea, emb_W, emb_b);
    k_zero <<<1, 384>>>();

    for (int l = 0; l < 3; l++) {
        const float* Wl = convW + (size_t)l*261*256;
        const float* bl = convB + l*256;
        k_convmm   <<<N_NODES/16, 256>>>(Wl, bl, l > 0,
                                         bn2g + (l-1)*128, bn2b + (l-1)*128,
                                         sum2p + (l-1)*128, sq2p + (l-1)*128);
        k_stats    <<<NM/256, 256>>>(Wl, idx, edge_fea,
                                     sum1p + l*128, sq1p + l*128);
        k_aggregate<<<N_NODES/8, 128>>>(Wl, idx, edge_fea,
                                        bn1g + l*256, bn1b + l*256,
                                        sum1p + l*128, sq1p + l*128,
                                        sum2p + l*128, sq2p + l*128);
    }

    k_piprep<<<1, 128>>>(W1, b1, tp_ptr);
    k_qgemm <<<N_NODES/16, 128>>>(W1, bn2g + 2*128, bn2b + 2*128,
                                  sum2p + 2*128, sq2p + 2*128);
    k_pimlp <<<NM/32, 256, 32768>>>(idx, edge_fea, distance, W2, b2, W3, b3, w4, b4);

    k_smax1<<<NM/256, 256>>>();
    k_smax2<<<1, 256>>>(NM/256);
    k_smax3<<<NM/256, 256>>>(out);

    (void)in_sizes; (void)n_in; (void)out_size;
}

// round 15
// speedup vs baseline: 1.0133x; 1.0133x over previous
#include <cuda_runtime.h>
#include <math.h>

#define N_NODES 30000
#define MM      16
#define NODEF   128
#define NM      (N_NODES*MM)   // 480000

typedef unsigned long long ull;

// ---------------- f32x2 packed helpers (sm_103a) ---------------------------
__device__ __forceinline__ ull pack2(float x, float y) {
    ull r; asm("mov.b64 %0, {%1, %2};" : "=l"(r) : "f"(x), "f"(y)); return r;
}
__device__ __forceinline__ void fma2(ull& d, ull a, ull b) {
    asm("fma.rn.f32x2 %0, %1, %2, %0;" : "+l"(d) : "l"(a), "l"(b));
}
__device__ __forceinline__ float2 unpack2(ull v) {
    float2 r; asm("mov.b64 {%0, %1}, %2;" : "=f"(r.x), "=f"(r.y) : "l"(v)); return r;
}
__device__ __forceinline__ float softplusf(float x) {
    float ax = fabsf(x);
    return fmaxf(x, 0.f) + __logf(1.f + __expf(-ax));
}

// ---------------- scratch (device globals; no allocations) ----------------
__device__ float  g_node[N_NODES*NODEF];
__device__ float  g_S[N_NODES*NODEF];
__device__ float  g_P[N_NODES*NODEF];
__device__ float  g_summed[N_NODES*NODEF];
__device__ float  g_Q[N_NODES*NODEF];
__device__ double g_sum1[3][NODEF], g_sq1[3][NODEF];
__device__ double g_sum2[3][NODEF], g_sq2[3][NODEF];
__device__ float  g_We[5*NODEF], g_wd[NODEF], g_cvec[NODEF];
__device__ float  g_logits[NM];
__device__ float  g_bmax[2048], g_bsum[2048];
__device__ float  g_gmax, g_ginv;
__device__ float  g_tp;

// ---------------- embedding: node = node_fea @ emb_W + emb_b --------------
__global__ void k_embed(const float* __restrict__ nf,
                        const float* __restrict__ W,
                        const float* __restrict__ b) {
    __shared__ float s[19];
    int n = blockIdx.x;
    if (threadIdx.x < 19) s[threadIdx.x] = nf[n*19 + threadIdx.x];
    __syncthreads();
    int c = threadIdx.x;
    float acc = b[c];
    #pragma unroll
    for (int k = 0; k < 19; k++) acc += s[k] * W[k*128 + c];
    g_node[n*128 + c] = acc;
}

__global__ void k_zero() {
    int i = threadIdx.x;                 // 384 threads cover 3*128
    int l = i >> 7, c = i & 127;
    g_sum1[l][c] = 0.0; g_sq1[l][c] = 0.0;
    g_sum2[l][c] = 0.0; g_sq2[l][c] = 0.0;
}

// ------- conv GEMM: S = node@Wself + bias, P = node@Wnbr (cols 0..127) ----
__global__ __launch_bounds__(256) void k_convmm(const float* __restrict__ Wl,
                                                const float* __restrict__ bl,
                                                int upd,
                                                const float* __restrict__ g2,
                                                const float* __restrict__ b2v,
                                                const double* __restrict__ sum2,
                                                const double* __restrict__ sq2) {
    __shared__ float sn[16*128];
    __shared__ float ssc[128], ssh[128];
    int tid = threadIdx.x;
    int r0  = blockIdx.x * 16;
    if (upd) {
        if (tid < 128) {
            double mean = sum2[tid] * (1.0/(double)N_NODES);
            double var  = sq2[tid]  * (1.0/(double)N_NODES) - mean*mean;
            float  sc   = g2[tid] * (float)(1.0 / sqrt(var + 1e-5));
            ssc[tid] = sc;
            ssh[tid] = b2v[tid] - (float)mean * sc;
        }
        __syncthreads();
        for (int i = tid; i < 2048; i += 256) {
            int c = i & 127;
            float x = g_node[r0*128 + i]
                    + g_summed[r0*128 + i]*ssc[c] + ssh[c];
            float v = softplusf(x);
            g_node[r0*128 + i] = v;
            sn[i] = v;
        }
    } else {
        for (int i = tid; i < 2048; i += 256) sn[i] = g_node[r0*128 + i];
    }
    __syncthreads();
    int half = tid >> 7, c = tid & 127;
    const float* W = Wl + (half*128)*256 + c;   // row stride 256, col c
    float acc[16];
    float bi = half ? 0.f : bl[c];
    #pragma unroll
    for (int r = 0; r < 16; r++) acc[r] = bi;
    for (int k = 0; k < 128; k += 2) {
        float w0 = W[k*256], w1 = W[(k+1)*256];
        #pragma unroll
        for (int r = 0; r < 16; r++) {
            float2 h = *(const float2*)&sn[r*128 + k];
            acc[r] += h.x*w0 + h.y*w1;
        }
    }
    float* out = half ? g_P : g_S;
    #pragma unroll
    for (int r = 0; r < 16; r++) out[(r0+r)*128 + c] = acc[r];
}

// -------- BN1 statistics; 256 threads = 2 half-blocks of 128 rows each ----
__global__ __launch_bounds__(256) void k_stats(const float* __restrict__ Wl,
                                               const int*   __restrict__ idx,
                                               const float* __restrict__ ef,
                                               double* __restrict__ sum1,
                                               double* __restrict__ sq1) {
    int tid = threadIdx.x;
    int c   = tid & 127;
    int hh  = tid >> 7;                 // half: rows hh*128 .. hh*128+127
    int r0  = blockIdx.x * 256;
    __shared__ int   sidx[256];
    __shared__ float sef[256][5];
    if (tid < 256) {
        int id = idx[r0 + tid];
        sidx[tid] = (id < 0) ? id + N_NODES : id;
    }
    for (int i = tid; i < 1280; i += 256) sef[i/5][i%5] = ef[r0*5 + i];
    __syncthreads();
    float we[5];
    #pragma unroll
    for (int e = 0; e < 5; e++) we[e] = Wl[(256+e)*256 + c];
    float fs = 0.f, fq = 0.f;
    int n0 = (r0 >> 4) + hh*8;
    int m0 = hh*128;
    for (int g = 0; g < 8; g++) {
        float sv = g_S[(n0+g)*128 + c];
        #pragma unroll 4
        for (int m = 0; m < 16; m++) {
            int row = m0 + g*16 + m;
            float v = sv + g_P[sidx[row]*128 + c];
            #pragma unroll
            for (int e = 0; e < 5; e++) v += sef[row][e] * we[e];
            fs += v; fq += v*v;
        }
    }
    __shared__ float rs[256], rq[256];
    rs[tid] = fs; rq[tid] = fq;
    __syncthreads();
    if (tid < 128) {
        double S = (double)rs[tid] + (double)rs[tid + 128];
        double Q = (double)rq[tid] + (double)rq[tid + 128];
        atomicAdd(&sum1[tid], S);
        atomicAdd(&sq1[tid],  Q);
    }
}

// ---- 8 nodes/block: summed + BN2 stats (fused colreduce), BN1 inline -----
__global__ __launch_bounds__(128) void k_aggregate(const float* __restrict__ Wl,
                                                   const int*   __restrict__ idx,
                                                   const float* __restrict__ ef,
                                                   const float* __restrict__ g1,
                                                   const float* __restrict__ b1v,
                                                   const double* __restrict__ sum1,
                                                   const double* __restrict__ sq1,
                                                   double* __restrict__ sum2,
                                                   double* __restrict__ sq2) {
    int c  = threadIdx.x;
    int n0 = blockIdx.x * 8;
    __shared__ int   sidx[128];
    __shared__ float smask[128];
    __shared__ float sef[128][5];
    {
        int id = idx[n0*16 + c];
        sidx[c]  = (id < 0) ? id + N_NODES : id;
        smask[c] = (id < 0) ? 0.f : 1.f;
    }
    for (int i = c; i < 640; i += 128) sef[i/5][i%5] = ef[n0*80 + i];
    __syncthreads();
    float we[5];
    #pragma unroll
    for (int e = 0; e < 5; e++) we[e] = Wl[(256+e)*256 + c];
    double mean = sum1[c] * (1.0/(double)NM);
    double var  = sq1[c]  * (1.0/(double)NM) - mean*mean;
    float  sc   = g1[c] * (float)(1.0 / sqrt(var + 1e-5));
    float  sh   = b1v[c] - (float)mean * sc;

    float s = 0.f, q = 0.f;
    for (int g = 0; g < 8; g++) {
        float sv = g_S[(n0+g)*128 + c];
        float acc = 0.f;
        #pragma unroll 4
        for (int m = 0; m < 16; m++) {
            int row = g*16 + m;
            float v = sv + g_P[sidx[row]*128 + c];
            #pragma unroll
            for (int e = 0; e < 5; e++) v += sef[row][e] * we[e];
            float a = v*sc + sh;
            float f = __fdividef(smask[row], 1.f + __expf(-a));
            acc += f*f;
        }
        g_summed[(n0+g)*128 + c] = acc;
        s += acc; q += acc*acc;
    }
    atomicAdd(&sum2[c], (double)s);
    atomicAdd(&sq2[c],  (double)q);
}

// ---------------- pi prep: fold tiled/repeated columns of W1 --------------
__global__ void k_piprep(const float* __restrict__ W1,
                         const float* __restrict__ b1,
                         const unsigned* __restrict__ tpp) {
    int c = threadIdx.x;
    unsigned u = *tpp;
    int iv = (int)u;
    float tp = (iv > -1000000 && iv < 1000000) ? (float)iv : __int_as_float(iv);
    if (c == 0) g_tp = tp;
    #pragma unroll
    for (int e = 0; e < 5; e++)
        g_We[e*128 + c] = W1[(128+e)*128 + c] + W1[(133+e)*128 + c];
    float wd = 0.f, ct = 0.f;
    for (int r = 138; r < 143; r++) wd += W1[r*128 + c];
    for (int r = 143; r < 148; r++) ct += W1[r*128 + c];
    g_wd[c]   = wd;
    g_cvec[c] = b1[c] + tp*ct;
}

// Q = update(node) @ W1[0:128] + cvec
__global__ __launch_bounds__(128) void k_qgemm(const float* __restrict__ W1,
                                               const float* __restrict__ g2,
                                               const float* __restrict__ b2v,
                                               const double* __restrict__ sum2,
                                               const double* __restrict__ sq2) {
    __shared__ float sn[2048];
    __shared__ float ssc[128], ssh[128];
    int tid = threadIdx.x;
    int r0  = blockIdx.x * 16;
    {
        double mean = sum2[tid] * (1.0/(double)N_NODES);
        double var  = sq2[tid]  * (1.0/(double)N_NODES) - mean*mean;
        float  scv  = g2[tid] * (float)(1.0 / sqrt(var + 1e-5));
        ssc[tid] = scv;
        ssh[tid] = b2v[tid] - (float)mean * scv;
    }
    __syncthreads();
    for (int i = tid; i < 2048; i += 128) {
        int c = i & 127;
        float x = g_node[r0*128 + i]
                + g_summed[r0*128 + i]*ssc[c] + ssh[c];
        sn[i] = softplusf(x);
    }
    __syncthreads();
    int c = tid;
    float cv = g_cvec[c];
    float acc[16];
    #pragma unroll
    for (int r = 0; r < 16; r++) acc[r] = cv;
    for (int k = 0; k < 128; k += 2) {
        float w0 = W1[k*128 + c], w1 = W1[(k+1)*128 + c];
        #pragma unroll
        for (int r = 0; r < 16; r++) {
            float2 h = *(const float2*)&sn[r*128 + k];
            acc[r] += h.x*w0 + h.y*w1;
        }
    }
    #pragma unroll
    for (int r = 0; r < 16; r++) g_Q[(r0+r)*128 + c] = acc[r];
}

// ----------- fused pi MLP: 32 rows/block, 256 threads, 32KB smem ----------
__global__ __launch_bounds__(256) void k_pimlp(const int*   __restrict__ idx,
                                               const float* __restrict__ ef,
                                               const float* __restrict__ dist,
                                               const float* __restrict__ W2,
                                               const float* __restrict__ b2,
                                               const float* __restrict__ W3,
                                               const float* __restrict__ b3,
                                               const float* __restrict__ w4,
                                               const float* __restrict__ b4) {
    extern __shared__ float sm[];
    float* hA = sm;             // 32*128: h1, then h2 half1
    float* hB = sm + 32*128;    // 32*128: h2 half0, then h3
    __shared__ int   sidx[32];
    __shared__ float sdist[32];
    __shared__ float sef[32][5];
    int tid = threadIdx.x;
    int r0  = blockIdx.x * 32;
    if (tid < 32) { sidx[tid] = idx[r0 + tid]; sdist[tid] = dist[r0 + tid]; }
    if (tid < 160) sef[tid/5][tid%5] = ef[r0*5 + tid];
    __syncthreads();

    // stage 1
    {
        int j = tid & 127, rh = tid >> 7;
        float we0 = g_We[j], we1 = g_We[128+j], we2 = g_We[256+j],
              we3 = g_We[384+j], we4 = g_We[512+j];
        float wd = g_wd[j];
        for (int r = rh*16; r < rh*16 + 16; r++) {
            int id = sidx[r];
            int p  = (id < 0) ? id + N_NODES : id;
            float v = g_Q[p*128 + j];
            v += sef[r][0]*we0 + sef[r][1]*we1 + sef[r][2]*we2
               + sef[r][3]*we3 + sef[r][4]*we4;
            v += sdist[r]*wd;
            hA[r*128 + j] = fmaxf(v, 0.f);
        }
    }
    __syncthreads();

    int cb = (tid & 31) * 4;
    int rb = (tid >> 5) * 4;

    // ---- stage 2: both halves in one pass over k -------------------------
    {
        ull acc2[4][4];
        #pragma unroll
        for (int r = 0; r < 4; r++)
            #pragma unroll
            for (int q = 0; q < 4; q++) acc2[r][q] = 0ull;
        const float* W2a = W2 + cb;
        const float* W2b = W2 + 128 + cb;
        for (int k = 0; k < 128; k += 2) {
            ulonglong2 wa0 = *(const ulonglong2*)(W2a + k*256);
            ulonglong2 wa1 = *(const ulonglong2*)(W2a + (k+1)*256);
            ulonglong2 wb0 = *(const ulonglong2*)(W2b + k*256);
            ulonglong2 wb1 = *(const ulonglong2*)(W2b + (k+1)*256);
            #pragma unroll
            for (int r = 0; r < 4; r++) {
                float2 h = *(const float2*)&hA[(rb+r)*128 + k];
                ull ha = pack2(h.x, h.x);
                ull hb = pack2(h.y, h.y);
                fma2(acc2[r][0], ha, wa0.x); fma2(acc2[r][1], ha, wa0.y);
                fma2(acc2[r][2], ha, wb0.x); fma2(acc2[r][3], ha, wb0.y);
                fma2(acc2[r][0], hb, wa1.x); fma2(acc2[r][1], hb, wa1.y);
                fma2(acc2[r][2], hb, wb1.x); fma2(acc2[r][3], hb, wb1.y);
            }
        }
        __syncthreads();
        const float2 ba0 = *(const float2*)&b2[cb];
        const float2 ba1 = *(const float2*)&b2[cb + 2];
        const float2 bb0 = *(const float2*)&b2[128 + cb];
        const float2 bb1 = *(const float2*)&b2[128 + cb + 2];
        #pragma unroll
        for (int r = 0; r < 4; r++) {
            float2 a0 = unpack2(acc2[r][0]);
            float2 a1 = unpack2(acc2[r][1]);
            float2 a2 = unpack2(acc2[r][2]);
            float2 a3 = unpack2(acc2[r][3]);
            float4 o0, o1;
            o0.x = fmaxf(a0.x + ba0.x, 0.f);
            o0.y = fmaxf(a0.y + ba0.y, 0.f);
            o0.z = fmaxf(a1.x + ba1.x, 0.f);
            o0.w = fmaxf(a1.y + ba1.y, 0.f);
            o1.x = fmaxf(a2.x + bb0.x, 0.f);
            o1.y = fmaxf(a2.y + bb0.y, 0.f);
            o1.z = fmaxf(a3.x + bb1.x, 0.f);
            o1.w = fmaxf(a3.y + bb1.y, 0.f);
            *(float4*)&hB[(rb+r)*128 + cb] = o0;
            *(float4*)&hA[(rb+r)*128 + cb] = o1;
        }
    }
    __syncthreads();

    // ---- stage 3: one pass over 256 k (hB then hA) -----------------------
    ull acc3[4][2];
    #pragma unroll
    for (int r = 0; r < 4; r++) { acc3[r][0] = 0ull; acc3[r][1] = 0ull; }
    {
        const float* W3c = W3 + cb;
        for (int k = 0; k < 128; k += 2) {
            ulonglong2 w0 = *(const ulonglong2*)(W3c + k*128);
            ulonglong2 w1 = *(const ulonglong2*)(W3c + (k+1)*128);
            #pragma unroll
            for (int r = 0; r < 4; r++) {
                float2 h = *(const float2*)&hB[(rb+r)*128 + k];
                ull ha = pack2(h.x, h.x);
                ull hb = pack2(h.y, h.y);
                fma2(acc3[r][0], ha, w0.x); fma2(acc3[r][1], ha, w0.y);
                fma2(acc3[r][0], hb, w1.x); fma2(acc3[r][1], hb, w1.y);
            }
        }
        const float* W3d = W3 + 128*128 + cb;
        for (int k = 0; k < 128; k += 2) {
            ulonglong2 w0 = *(const ulonglong2*)(W3d + k*128);
            ulonglong2 w1 = *(const ulonglong2*)(W3d + (k+1)*128);
            #pragma unroll
            for (int r = 0; r < 4; r++) {
                float2 h = *(const float2*)&hA[(rb+r)*128 + k];
                ull ha = pack2(h.x, h.x);
                ull hb = pack2(h.y, h.y);
                fma2(acc3[r][0], ha, w0.x); fma2(acc3[r][1], ha, w0.y);
                fma2(acc3[r][0], hb, w1.x); fma2(acc3[r][1], hb, w1.y);
            }
        }
    }
    __syncthreads();

    {
        const float2 bb0 = *(const float2*)&b3[cb];
        const float2 bb1 = *(const float2*)&b3[cb + 2];
        #pragma unroll
        for (int r = 0; r < 4; r++) {
            float2 a0 = unpack2(acc3[r][0]);
            float2 a1 = unpack2(acc3[r][1]);
            float4 o;
            o.x = fmaxf(a0.x + bb0.x, 0.f);
            o.y = fmaxf(a0.y + bb0.y, 0.f);
            o.z = fmaxf(a1.x + bb1.x, 0.f);
            o.w = fmaxf(a1.y + bb1.y, 0.f);
            *(float4*)&hB[(rb+r)*128 + cb] = o;
        }
    }
    __syncthreads();

    // stage 4: logits + validity mask
    {
        int warp = tid >> 5, lane = tid & 31;
        float w4a = w4[lane], w4b = w4[lane+32], w4c = w4[lane+64], w4d = w4[lane+96];
        float tp = g_tp;
        for (int r = warp*4; r < warp*4 + 4; r++) {
            const float* h = &hB[r*128];
            float v = h[lane]*w4a + h[lane+32]*w4b + h[lane+64]*w4c + h[lane+96]*w4d;
            #pragma unroll
            for (int o = 16; o > 0; o >>= 1) v += __shfl_down_sync(0xffffffffu, v, o);
            if (lane == 0) {
                float lg = v + b4[0];
                int id = sidx[r];
                if (!(id >= 0 && sef[r][4] <= tp)) lg -= 1e8f;
                g_logits[r0 + r] = lg;
            }
        }
    }
}

// ---------------- global masked softmax over 480000 logits ----------------
__global__ void k_smax1() {
    __shared__ float red[256];
    int tid = threadIdx.x;
    int i = blockIdx.x*256 + tid;
    float v = g_logits[i];
    red[tid] = v; __syncthreads();
    for (int s = 128; s > 0; s >>= 1) {
        if (tid < s) red[tid] = fmaxf(red[tid], red[tid+s]);
        __syncthreads();
    }
    float bm = red[0];
    __syncthreads();
    float e = __expf(v - bm);
    red[tid] = e; __syncthreads();
    for (int s = 128; s > 0; s >>= 1) {
        if (tid < s) red[tid] += red[tid+s];
        __syncthreads();
    }
    if (tid == 0) { g_bmax[blockIdx.x] = bm; g_bsum[blockIdx.x] = red[0]; }
}

__global__ void k_smax2(int nb) {
    __shared__ float red[256];
    int tid = threadIdx.x;
    float m = -3.4e38f;
    for (int i = tid; i < nb; i += 256) m = fmaxf(m, g_bmax[i]);
    red[tid] = m; __syncthreads();
    for (int s = 128; s > 0; s >>= 1) {
        if (tid < s) red[tid] = fmaxf(red[tid], red[tid+s]);
        __syncthreads();
    }
    float gm = red[0];
    __syncthreads();
    float su = 0.f;
    for (int i = tid; i < nb; i += 256) su += g_bsum[i]*__expf(g_bmax[i] - gm);
    red[tid] = su; __syncthreads();
    for (int s = 128; s > 0; s >>= 1) {
        if (tid < s) red[tid] += red[tid+s];
        __syncthreads();
    }
    if (tid == 0) { g_gmax = gm; g_ginv = 1.0f / red[0]; }
}

__global__ void k_smax3(float* __restrict__ out) {
    int i = blockIdx.x*256 + threadIdx.x;
    out[i] = __expf(g_logits[i] - g_gmax) * g_ginv;
}

// --------------------------------- launch ---------------------------------
extern "C" void kernel_launch(void* const* d_in, const int* in_sizes, int n_in,
                              void* d_out, int out_size) {
    const float* node_fea = (const float*)d_in[0];
    const float* edge_fea = (const float*)d_in[1];
    const int*   idx      = (const int*)  d_in[2];
    const float* distance = (const float*)d_in[3];
    const unsigned* tp_ptr = (const unsigned*)d_in[4];
    const float* emb_W = (const float*)d_in[5];
    const float* emb_b = (const float*)d_in[6];
    const float* convW = (const float*)d_in[7];
    const float* convB = (const float*)d_in[8];
    const float* bn1g  = (const float*)d_in[9];
    const float* bn1b  = (const float*)d_in[10];
    const float* bn2g  = (const float*)d_in[11];
    const float* bn2b  = (const float*)d_in[12];
    const float* W1 = (const float*)d_in[13];
    const float* b1 = (const float*)d_in[14];
    const float* W2 = (const float*)d_in[15];
    const float* b2 = (const float*)d_in[16];
    const float* W3 = (const float*)d_in[17];
    const float* b3 = (const float*)d_in[18];
    const float* w4 = (const float*)d_in[19];
    const float* b4 = (const float*)d_in[20];
    float* out = (float*)d_out;

    double *sum1p, *sq1p, *sum2p, *sq2p;
    cudaGetSymbolAddress((void**)&sum1p, g_sum1);
    cudaGetSymbolAddress((void**)&sq1p,  g_sq1);
    cudaGetSymbolAddress((void**)&sum2p, g_sum2);
    cudaGetSymbolAddress((void**)&sq2p,  g_sq2);

    k_embed<<<N_NODES, 128>>>(node_fea, emb_W, emb_b);
    k_zero <<<1, 384>>>();

    for (int l = 0; l < 3; l++) {
        const float* Wl = convW + (size_t)l*261*256;
        const float* bl = convB + l*256;
        k_convmm   <<<N_NODES/16, 256>>>(Wl, bl, l > 0,
                                         bn2g + (l-1)*128, bn2b + (l-1)*128,
                                         sum2p + (l-1)*128, sq2p + (l-1)*128);
        k_stats    <<<NM/256, 256>>>(Wl, idx, edge_fea,
                                     sum1p + l*128, sq1p + l*128);
        k_aggregate<<<N_NODES/8, 128>>>(Wl, idx, edge_fea,
                                        bn1g + l*256, bn1b + l*256,
                                        sum1p + l*128, sq1p + l*128,
                                        sum2p + l*128, sq2p + l*128);
    }

    k_piprep<<<1, 128>>>(W1, b1, tp_ptr);
    k_qgemm <<<N_NODES/16, 128>>>(W1, bn2g + 2*128, bn2b + 2*128,
                                  sum2p + 2*128, sq2p + 2*128);
    k_pimlp <<<NM/32, 256, 32768>>>(idx, edge_fea, distance, W2, b2, W3, b3, w4, b4);

    k_smax1<<<NM/256, 256>>>();
    k_smax2<<<1, 256>>>(NM/256);
    k_smax3<<<NM/256, 256>>>(out);

    (void)in_sizes; (void)n_in; (void)out_size;
}

// round 16
// speedup vs baseline: 1.0419x; 1.0282x over previous
#include <cuda_runtime.h>
#include <math.h>

#define N_NODES 30000
#define MM      16
#define NODEF   128
#define NM      (N_NODES*MM)   // 480000

typedef unsigned long long ull;

// ---------------- f32x2 packed helpers (sm_103a) ---------------------------
__device__ __forceinline__ ull pack2(float x, float y) {
    ull r; asm("mov.b64 %0, {%1, %2};" : "=l"(r) : "f"(x), "f"(y)); return r;
}
__device__ __forceinline__ void fma2(ull& d, ull a, ull b) {
    asm("fma.rn.f32x2 %0, %1, %2, %0;" : "+l"(d) : "l"(a), "l"(b));
}
__device__ __forceinline__ float2 unpack2(ull v) {
    float2 r; asm("mov.b64 {%0, %1}, %2;" : "=f"(r.x), "=f"(r.y) : "l"(v)); return r;
}
__device__ __forceinline__ float softplusf(float x) {
    float ax = fabsf(x);
    return fmaxf(x, 0.f) + __logf(1.f + __expf(-ax));
}

// ---------------- scratch (device globals; no allocations) ----------------
__device__ float  g_node[N_NODES*NODEF];
__device__ float  g_S[N_NODES*NODEF];
__device__ float  g_P[N_NODES*NODEF];
__device__ float  g_summed[N_NODES*NODEF];
__device__ float  g_Q[N_NODES*NODEF];
__device__ double g_sum1[3][NODEF], g_sq1[3][NODEF];
__device__ double g_sum2[3][NODEF], g_sq2[3][NODEF];
__device__ float  g_We[5*NODEF], g_wd[NODEF], g_cvec[NODEF];
__device__ float  g_logits[NM];
__device__ float  g_bmax[2048], g_bsum[2048];
__device__ float  g_gmax, g_ginv;
__device__ float  g_tp;

// ---------------- embedding: node = node_fea @ emb_W + emb_b --------------
__global__ void k_embed(const float* __restrict__ nf,
                        const float* __restrict__ W,
                        const float* __restrict__ b) {
    __shared__ float s[19];
    int n = blockIdx.x;
    if (threadIdx.x < 19) s[threadIdx.x] = nf[n*19 + threadIdx.x];
    __syncthreads();
    int c = threadIdx.x;
    float acc = b[c];
    #pragma unroll
    for (int k = 0; k < 19; k++) acc += s[k] * W[k*128 + c];
    g_node[n*128 + c] = acc;
}

__global__ void k_zero() {
    int i = threadIdx.x;                 // 384 threads cover 3*128
    int l = i >> 7, c = i & 127;
    g_sum1[l][c] = 0.0; g_sq1[l][c] = 0.0;
    g_sum2[l][c] = 0.0; g_sq2[l][c] = 0.0;
}

// ------- conv GEMM: S = node@Wself + bias, P = node@Wnbr (cols 0..127) ----
__global__ __launch_bounds__(256) void k_convmm(const float* __restrict__ Wl,
                                                const float* __restrict__ bl,
                                                int upd,
                                                const float* __restrict__ g2,
                                                const float* __restrict__ b2v,
                                                const double* __restrict__ sum2,
                                                const double* __restrict__ sq2) {
    __shared__ float sn[16*128];
    __shared__ float ssc[128], ssh[128];
    int tid = threadIdx.x;
    int r0  = blockIdx.x * 16;
    if (upd) {
        if (tid < 128) {
            double mean = sum2[tid] * (1.0/(double)N_NODES);
            double var  = sq2[tid]  * (1.0/(double)N_NODES) - mean*mean;
            float  sc   = g2[tid] * (float)(1.0 / sqrt(var + 1e-5));
            ssc[tid] = sc;
            ssh[tid] = b2v[tid] - (float)mean * sc;
        }
        __syncthreads();
        for (int i = tid; i < 2048; i += 256) {
            int c = i & 127;
            float x = g_node[r0*128 + i]
                    + g_summed[r0*128 + i]*ssc[c] + ssh[c];
            float v = softplusf(x);
            g_node[r0*128 + i] = v;
            sn[i] = v;
        }
    } else {
        for (int i = tid; i < 2048; i += 256) sn[i] = g_node[r0*128 + i];
    }
    __syncthreads();
    int half = tid >> 7, c = tid & 127;
    const float* W = Wl + (half*128)*256 + c;   // row stride 256, col c
    float acc[16];
    float bi = half ? 0.f : bl[c];
    #pragma unroll
    for (int r = 0; r < 16; r++) acc[r] = bi;
    for (int k = 0; k < 128; k += 2) {
        float w0 = W[k*256], w1 = W[(k+1)*256];
        #pragma unroll
        for (int r = 0; r < 16; r++) {
            float2 h = *(const float2*)&sn[r*128 + k];
            acc[r] += h.x*w0 + h.y*w1;
        }
    }
    float* out = half ? g_P : g_S;
    #pragma unroll
    for (int r = 0; r < 16; r++) out[(r0+r)*128 + c] = acc[r];
}

// -------- BN1 statistics; 256 threads = 2 half-blocks of 128 rows each ----
__global__ __launch_bounds__(256) void k_stats(const float* __restrict__ Wl,
                                               const int*   __restrict__ idx,
                                               const float* __restrict__ ef,
                                               double* __restrict__ sum1,
                                               double* __restrict__ sq1) {
    int tid = threadIdx.x;
    int c   = tid & 127;
    int hh  = tid >> 7;                 // half: rows hh*128 .. hh*128+127
    int r0  = blockIdx.x * 256;
    __shared__ int   sidx[256];
    __shared__ float sef[256][5];
    if (tid < 256) {
        int id = idx[r0 + tid];
        sidx[tid] = (id < 0) ? id + N_NODES : id;
    }
    for (int i = tid; i < 1280; i += 256) sef[i/5][i%5] = ef[r0*5 + i];
    __syncthreads();
    float we[5];
    #pragma unroll
    for (int e = 0; e < 5; e++) we[e] = Wl[(256+e)*256 + c];
    float fs = 0.f, fq = 0.f;
    int n0 = (r0 >> 4) + hh*8;
    int m0 = hh*128;
    for (int g = 0; g < 8; g++) {
        float sv = g_S[(n0+g)*128 + c];
        #pragma unroll 4
        for (int m = 0; m < 16; m++) {
            int row = m0 + g*16 + m;
            float v = sv + g_P[sidx[row]*128 + c];
            #pragma unroll
            for (int e = 0; e < 5; e++) v += sef[row][e] * we[e];
            fs += v; fq += v*v;
        }
    }
    __shared__ float rs[256], rq[256];
    rs[tid] = fs; rq[tid] = fq;
    __syncthreads();
    if (tid < 128) {
        double S = (double)rs[tid] + (double)rs[tid + 128];
        double Q = (double)rq[tid] + (double)rq[tid + 128];
        atomicAdd(&sum1[tid], S);
        atomicAdd(&sq1[tid],  Q);
    }
}

// ---- 16 nodes/block, 256 threads (2 half-blocks of 8 nodes); BN1 inline,
// ---- summed + BN2 stats with shared-combine + single atomic per channel --
__global__ __launch_bounds__(256) void k_aggregate(const float* __restrict__ Wl,
                                                   const int*   __restrict__ idx,
                                                   const float* __restrict__ ef,
                                                   const float* __restrict__ g1,
                                                   const float* __restrict__ b1v,
                                                   const double* __restrict__ sum1,
                                                   const double* __restrict__ sq1,
                                                   double* __restrict__ sum2,
                                                   double* __restrict__ sq2) {
    int tid = threadIdx.x;
    int c   = tid & 127;
    int hh  = tid >> 7;
    int n0  = blockIdx.x * 16;
    __shared__ int   sidx[256];
    __shared__ float smask[256];
    __shared__ float sef[256][5];
    {
        int id = idx[n0*16 + tid];
        sidx[tid]  = (id < 0) ? id + N_NODES : id;
        smask[tid] = (id < 0) ? 0.f : 1.f;
    }
    for (int i = tid; i < 1280; i += 256) sef[i/5][i%5] = ef[n0*80 + i];
    __syncthreads();
    float we[5];
    #pragma unroll
    for (int e = 0; e < 5; e++) we[e] = Wl[(256+e)*256 + c];
    double mean = sum1[c] * (1.0/(double)NM);
    double var  = sq1[c]  * (1.0/(double)NM) - mean*mean;
    float  sc   = g1[c] * (float)(1.0 / sqrt(var + 1e-5));
    float  sh   = b1v[c] - (float)mean * sc;

    int nb = n0 + hh*8;      // this half's first node
    int m0 = hh*128;         // this half's first row in shared tables
    float s = 0.f, q = 0.f;
    for (int g = 0; g < 8; g++) {
        float sv = g_S[(nb+g)*128 + c];
        float acc = 0.f;
        #pragma unroll 4
        for (int m = 0; m < 16; m++) {
            int row = m0 + g*16 + m;
            float v = sv + g_P[sidx[row]*128 + c];
            #pragma unroll
            for (int e = 0; e < 5; e++) v += sef[row][e] * we[e];
            float a = v*sc + sh;
            float f = __fdividef(smask[row], 1.f + __expf(-a));
            acc += f*f;
        }
        g_summed[(nb+g)*128 + c] = acc;
        s += acc; q += acc*acc;
    }
    __shared__ float rs[256], rq[256];
    rs[tid] = s; rq[tid] = q;
    __syncthreads();
    if (tid < 128) {
        double S = (double)rs[tid] + (double)rs[tid + 128];
        double Q = (double)rq[tid] + (double)rq[tid + 128];
        atomicAdd(&sum2[tid], S);
        atomicAdd(&sq2[tid],  Q);
    }
}

// ---------------- pi prep: fold tiled/repeated columns of W1 --------------
__global__ void k_piprep(const float* __restrict__ W1,
                         const float* __restrict__ b1,
                         const unsigned* __restrict__ tpp) {
    int c = threadIdx.x;
    unsigned u = *tpp;
    int iv = (int)u;
    float tp = (iv > -1000000 && iv < 1000000) ? (float)iv : __int_as_float(iv);
    if (c == 0) g_tp = tp;
    #pragma unroll
    for (int e = 0; e < 5; e++)
        g_We[e*128 + c] = W1[(128+e)*128 + c] + W1[(133+e)*128 + c];
    float wd = 0.f, ct = 0.f;
    for (int r = 138; r < 143; r++) wd += W1[r*128 + c];
    for (int r = 143; r < 148; r++) ct += W1[r*128 + c];
    g_wd[c]   = wd;
    g_cvec[c] = b1[c] + tp*ct;
}

// Q = update(node) @ W1[0:128] + cvec   (256 threads: 2 row-halves x 8 rows)
__global__ __launch_bounds__(256) void k_qgemm(const float* __restrict__ W1,
                                               const float* __restrict__ g2,
                                               const float* __restrict__ b2v,
                                               const double* __restrict__ sum2,
                                               const double* __restrict__ sq2) {
    __shared__ float sn[2048];
    __shared__ float ssc[128], ssh[128];
    int tid = threadIdx.x;
    int c   = tid & 127;
    int rh  = tid >> 7;
    int r0  = blockIdx.x * 16;
    if (tid < 128) {
        double mean = sum2[tid] * (1.0/(double)N_NODES);
        double var  = sq2[tid]  * (1.0/(double)N_NODES) - mean*mean;
        float  scv  = g2[tid] * (float)(1.0 / sqrt(var + 1e-5));
        ssc[tid] = scv;
        ssh[tid] = b2v[tid] - (float)mean * scv;
    }
    __syncthreads();
    for (int i = tid; i < 2048; i += 256) {
        int cc = i & 127;
        float x = g_node[r0*128 + i]
                + g_summed[r0*128 + i]*ssc[cc] + ssh[cc];
        sn[i] = softplusf(x);
    }
    __syncthreads();
    float cv = g_cvec[c];
    float acc[8];
    #pragma unroll
    for (int r = 0; r < 8; r++) acc[r] = cv;
    const float* hbase = &sn[rh*8*128];
    for (int k = 0; k < 128; k += 2) {
        float w0 = W1[k*128 + c], w1 = W1[(k+1)*128 + c];
        #pragma unroll
        for (int r = 0; r < 8; r++) {
            float2 h = *(const float2*)&hbase[r*128 + k];
            acc[r] += h.x*w0 + h.y*w1;
        }
    }
    #pragma unroll
    for (int r = 0; r < 8; r++) g_Q[(r0 + rh*8 + r)*128 + c] = acc[r];
}

// ----------- fused pi MLP: 32 rows/block, 256 threads, 32KB smem ----------
__global__ __launch_bounds__(256) void k_pimlp(const int*   __restrict__ idx,
                                               const float* __restrict__ ef,
                                               const float* __restrict__ dist,
                                               const float* __restrict__ W2,
                                               const float* __restrict__ b2,
                                               const float* __restrict__ W3,
                                               const float* __restrict__ b3,
                                               const float* __restrict__ w4,
                                               const float* __restrict__ b4) {
    extern __shared__ float sm[];
    float* hA = sm;             // 32*128: h1, then h2 half1
    float* hB = sm + 32*128;    // 32*128: h2 half0, then h3
    __shared__ int   sidx[32];
    __shared__ float sdist[32];
    __shared__ float sef[32][5];
    int tid = threadIdx.x;
    int r0  = blockIdx.x * 32;
    if (tid < 32) { sidx[tid] = idx[r0 + tid]; sdist[tid] = dist[r0 + tid]; }
    if (tid < 160) sef[tid/5][tid%5] = ef[r0*5 + tid];
    __syncthreads();

    // stage 1
    {
        int j = tid & 127, rh = tid >> 7;
        float we0 = g_We[j], we1 = g_We[128+j], we2 = g_We[256+j],
              we3 = g_We[384+j], we4 = g_We[512+j];
        float wd = g_wd[j];
        for (int r = rh*16; r < rh*16 + 16; r++) {
            int id = sidx[r];
            int p  = (id < 0) ? id + N_NODES : id;
            float v = g_Q[p*128 + j];
            v += sef[r][0]*we0 + sef[r][1]*we1 + sef[r][2]*we2
               + sef[r][3]*we3 + sef[r][4]*we4;
            v += sdist[r]*wd;
            hA[r*128 + j] = fmaxf(v, 0.f);
        }
    }
    __syncthreads();

    int cb = (tid & 31) * 4;
    int rb = (tid >> 5) * 4;

    // ---- stage 2: both halves in one pass over k -------------------------
    {
        ull acc2[4][4];
        #pragma unroll
        for (int r = 0; r < 4; r++)
            #pragma unroll
            for (int q = 0; q < 4; q++) acc2[r][q] = 0ull;
        const float* W2a = W2 + cb;
        const float* W2b = W2 + 128 + cb;
        for (int k = 0; k < 128; k += 2) {
            ulonglong2 wa0 = *(const ulonglong2*)(W2a + k*256);
            ulonglong2 wa1 = *(const ulonglong2*)(W2a + (k+1)*256);
            ulonglong2 wb0 = *(const ulonglong2*)(W2b + k*256);
            ulonglong2 wb1 = *(const ulonglong2*)(W2b + (k+1)*256);
            #pragma unroll
            for (int r = 0; r < 4; r++) {
                float2 h = *(const float2*)&hA[(rb+r)*128 + k];
                ull ha = pack2(h.x, h.x);
                ull hb = pack2(h.y, h.y);
                fma2(acc2[r][0], ha, wa0.x); fma2(acc2[r][1], ha, wa0.y);
                fma2(acc2[r][2], ha, wb0.x); fma2(acc2[r][3], ha, wb0.y);
                fma2(acc2[r][0], hb, wa1.x); fma2(acc2[r][1], hb, wa1.y);
                fma2(acc2[r][2], hb, wb1.x); fma2(acc2[r][3], hb, wb1.y);
            }
        }
        __syncthreads();
        const float2 ba0 = *(const float2*)&b2[cb];
        const float2 ba1 = *(const float2*)&b2[cb + 2];
        const float2 bb0 = *(const float2*)&b2[128 + cb];
        const float2 bb1 = *(const float2*)&b2[128 + cb + 2];
        #pragma unroll
        for (int r = 0; r < 4; r++) {
            float2 a0 = unpack2(acc2[r][0]);
            float2 a1 = unpack2(acc2[r][1]);
            float2 a2 = unpack2(acc2[r][2]);
            float2 a3 = unpack2(acc2[r][3]);
            float4 o0, o1;
            o0.x = fmaxf(a0.x + ba0.x, 0.f);
            o0.y = fmaxf(a0.y + ba0.y, 0.f);
            o0.z = fmaxf(a1.x + ba1.x, 0.f);
            o0.w = fmaxf(a1.y + ba1.y, 0.f);
            o1.x = fmaxf(a2.x + bb0.x, 0.f);
            o1.y = fmaxf(a2.y + bb0.y, 0.f);
            o1.z = fmaxf(a3.x + bb1.x, 0.f);
            o1.w = fmaxf(a3.y + bb1.y, 0.f);
            *(float4*)&hB[(rb+r)*128 + cb] = o0;
            *(float4*)&hA[(rb+r)*128 + cb] = o1;
        }
    }
    __syncthreads();

    // ---- stage 3: one pass over 256 k (hB then hA) -----------------------
    ull acc3[4][2];
    #pragma unroll
    for (int r = 0; r < 4; r++) { acc3[r][0] = 0ull; acc3[r][1] = 0ull; }
    {
        const float* W3c = W3 + cb;
        for (int k = 0; k < 128; k += 2) {
            ulonglong2 w0 = *(const ulonglong2*)(W3c + k*128);
            ulonglong2 w1 = *(const ulonglong2*)(W3c + (k+1)*128);
            #pragma unroll
            for (int r = 0; r < 4; r++) {
                float2 h = *(const float2*)&hB[(rb+r)*128 + k];
                ull ha = pack2(h.x, h.x);
                ull hb = pack2(h.y, h.y);
                fma2(acc3[r][0], ha, w0.x); fma2(acc3[r][1], ha, w0.y);
                fma2(acc3[r][0], hb, w1.x); fma2(acc3[r][1], hb, w1.y);
            }
        }
        const float* W3d = W3 + 128*128 + cb;
        for (int k = 0; k < 128; k += 2) {
            ulonglong2 w0 = *(const ulonglong2*)(W3d + k*128);
            ulonglong2 w1 = *(const ulonglong2*)(W3d + (k+1)*128);
            #pragma unroll
            for (int r = 0; r < 4; r++) {
                float2 h = *(const float2*)&hA[(rb+r)*128 + k];
                ull ha = pack2(h.x, h.x);
                ull hb = pack2(h.y, h.y);
                fma2(acc3[r][0], ha, w0.x); fma2(acc3[r][1], ha, w0.y);
                fma2(acc3[r][0], hb, w1.x); fma2(acc3[r][1], hb, w1.y);
            }
        }
    }
    __syncthreads();

    {
        const float2 bb0 = *(const float2*)&b3[cb];
        const float2 bb1 = *(const float2*)&b3[cb + 2];
        #pragma unroll
        for (int r = 0; r < 4; r++) {
            float2 a0 = unpack2(acc3[r][0]);
            float2 a1 = unpack2(acc3[r][1]);
            float4 o;
            o.x = fmaxf(a0.x + bb0.x, 0.f);
            o.y = fmaxf(a0.y + bb0.y, 0.f);
            o.z = fmaxf(a1.x + bb1.x, 0.f);
            o.w = fmaxf(a1.y + bb1.y, 0.f);
            *(float4*)&hB[(rb+r)*128 + cb] = o;
        }
    }
    __syncthreads();

    // stage 4: logits + validity mask
    {
        int warp = tid >> 5, lane = tid & 31;
        float w4a = w4[lane], w4b = w4[lane+32], w4c = w4[lane+64], w4d = w4[lane+96];
        float tp = g_tp;
        for (int r = warp*4; r < warp*4 + 4; r++) {
            const float* h = &hB[r*128];
            float v = h[lane]*w4a + h[lane+32]*w4b + h[lane+64]*w4c + h[lane+96]*w4d;
            #pragma unroll
            for (int o = 16; o > 0; o >>= 1) v += __shfl_down_sync(0xffffffffu, v, o);
            if (lane == 0) {
                float lg = v + b4[0];
                int id = sidx[r];
                if (!(id >= 0 && sef[r][4] <= tp)) lg -= 1e8f;
                g_logits[r0 + r] = lg;
            }
        }
    }
}

// ---------------- global masked softmax over 480000 logits ----------------
__global__ void k_smax1() {
    __shared__ float red[256];
    int tid = threadIdx.x;
    int i = blockIdx.x*256 + tid;
    float v = g_logits[i];
    red[tid] = v; __syncthreads();
    for (int s = 128; s > 0; s >>= 1) {
        if (tid < s) red[tid] = fmaxf(red[tid], red[tid+s]);
        __syncthreads();
    }
    float bm = red[0];
    __syncthreads();
    float e = __expf(v - bm);
    red[tid] = e; __syncthreads();
    for (int s = 128; s > 0; s >>= 1) {
        if (tid < s) red[tid] += red[tid+s];
        __syncthreads();
    }
    if (tid == 0) { g_bmax[blockIdx.x] = bm; g_bsum[blockIdx.x] = red[0]; }
}

__global__ void k_smax2(int nb) {
    __shared__ float red[256];
    int tid = threadIdx.x;
    float m = -3.4e38f;
    for (int i = tid; i < nb; i += 256) m = fmaxf(m, g_bmax[i]);
    red[tid] = m; __syncthreads();
    for (int s = 128; s > 0; s >>= 1) {
        if (tid < s) red[tid] = fmaxf(red[tid], red[tid+s]);
        __syncthreads();
    }
    float gm = red[0];
    __syncthreads();
    float su = 0.f;
    for (int i = tid; i < nb; i += 256) su += g_bsum[i]*__expf(g_bmax[i] - gm);
    red[tid] = su; __syncthreads();
    for (int s = 128; s > 0; s >>= 1) {
        if (tid < s) red[tid] += red[tid+s];
        __syncthreads();
    }
    if (tid == 0) { g_gmax = gm; g_ginv = 1.0f / red[0]; }
}

__global__ void k_smax3(float* __restrict__ out) {
    int i = blockIdx.x*256 + threadIdx.x;
    out[i] = __expf(g_logits[i] - g_gmax) * g_ginv;
}

// --------------------------------- launch ---------------------------------
extern "C" void kernel_launch(void* const* d_in, const int* in_sizes, int n_in,
                              void* d_out, int out_size) {
    const float* node_fea = (const float*)d_in[0];
    const float* edge_fea = (const float*)d_in[1];
    const int*   idx      = (const int*)  d_in[2];
    const float* distance = (const float*)d_in[3];
    const unsigned* tp_ptr = (const unsigned*)d_in[4];
    const float* emb_W = (const float*)d_in[5];
    const float* emb_b = (const float*)d_in[6];
    const float* convW = (const float*)d_in[7];
    const float* convB = (const float*)d_in[8];
    const float* bn1g  = (const float*)d_in[9];
    const float* bn1b  = (const float*)d_in[10];
    const float* bn2g  = (const float*)d_in[11];
    const float* bn2b  = (const float*)d_in[12];
    const float* W1 = (const float*)d_in[13];
    const float* b1 = (const float*)d_in[14];
    const float* W2 = (const float*)d_in[15];
    const float* b2 = (const float*)d_in[16];
    const float* W3 = (const float*)d_in[17];
    const float* b3 = (const float*)d_in[18];
    const float* w4 = (const float*)d_in[19];
    const float* b4 = (const float*)d_in[20];
    float* out = (float*)d_out;

    double *sum1p, *sq1p, *sum2p, *sq2p;
    cudaGetSymbolAddress((void**)&sum1p, g_sum1);
    cudaGetSymbolAddress((void**)&sq1p,  g_sq1);
    cudaGetSymbolAddress((void**)&sum2p, g_sum2);
    cudaGetSymbolAddress((void**)&sq2p,  g_sq2);

    k_embed<<<N_NODES, 128>>>(node_fea, emb_W, emb_b);
    k_zero <<<1, 384>>>();

    for (int l = 0; l < 3; l++) {
        const float* Wl = convW + (size_t)l*261*256;
        const float* bl = convB + l*256;
        k_convmm   <<<N_NODES/16, 256>>>(Wl, bl, l > 0,
                                         bn2g + (l-1)*128, bn2b + (l-1)*128,
                                         sum2p + (l-1)*128, sq2p + (l-1)*128);
        k_stats    <<<NM/256, 256>>>(Wl, idx, edge_fea,
                                     sum1p + l*128, sq1p + l*128);
        k_aggregate<<<N_NODES/16, 256>>>(Wl, idx, edge_fea,
                                         bn1g + l*256, bn1b + l*256,
                                         sum1p + l*128, sq1p + l*128,
                                         sum2p + l*128, sq2p + l*128);
    }

    k_piprep<<<1, 128>>>(W1, b1, tp_ptr);
    k_qgemm <<<N_NODES/16, 256>>>(W1, bn2g + 2*128, bn2b + 2*128,
                                  sum2p + 2*128, sq2p + 2*128);
    k_pimlp <<<NM/32, 256, 32768>>>(idx, edge_fea, distance, W2, b2, W3, b3, w4, b4);

    k_smax1<<<NM/256, 256>>>();
    k_smax2<<<1, 256>>>(NM/256);
    k_smax3<<<NM/256, 256>>>(out);

    (void)in_sizes; (void)n_in; (void)out_size;
}